// round 1
// baseline (speedup 1.0000x reference)
#include <cuda_runtime.h>

// Problem constants
#define TB 2
#define TT 2048
#define TC 768
#define TH 12
#define TD 64
#define TM 4096              // B*T
#define TSZ 3145728          // B*T*C = per-tensor element count
#define HSTRIDE 131072       // T*D = 2048*64

// Scratch: 9 qkv tensors (qn,kn,vn, ql,kl,vl, qh,kh,vh), 9 attention outputs
// (combos 0..7 + nominal at 8), lo/hi reduction.
__device__ float g_qkv[9 * TSZ];
__device__ float g_att[9 * TSZ];
__device__ float g_red[2 * TSZ];

typedef unsigned long long u64;

__device__ __forceinline__ u64 pk2(float a, float b) {
    u64 r; asm("mov.b64 %0,{%1,%2};" : "=l"(r) : "f"(a), "f"(b)); return r;
}
__device__ __forceinline__ float2 upk2(u64 v) {
    float2 f; asm("mov.b64 {%0,%1},%2;" : "=f"(f.x), "=f"(f.y) : "l"(v)); return f;
}
__device__ __forceinline__ u64 fma2(u64 a, u64 b, u64 c) {
    u64 d; asm("fma.rn.f32x2 %0,%1,%2,%3;" : "=l"(d) : "l"(a), "l"(b), "l"(c)); return d;
}
__device__ __forceinline__ u64 mul2(u64 a, u64 b) {
    u64 d; asm("mul.rn.f32x2 %0,%1,%2;" : "=l"(d) : "l"(a), "l"(b)); return d;
}

__device__ __forceinline__ void st4(float (*sm)[68], int kc, int lr, float4 v) {
    sm[kc + 0][lr] = v.x; sm[kc + 1][lr] = v.y;
    sm[kc + 2][lr] = v.z; sm[kc + 3][lr] = v.w;
}

// ============================================================================
// Kernel 1: fused QKV GEMM.
//   acc_n = x   @ W^T        (nominal)
//   acc_m = mid @ W^T        mid = (xl+xu)/2
//   acc_r = rad @ |W|^T      rad = (xu-xl)/2
//   lo = acc_m - acc_r ; hi = acc_m + acc_r
// M=4096, N=2304, K=768. BM=BN=64, BK=16, 256 threads, 4x4 microtile x3 accs.
// Epilogue scatters into head layout [b][h][t][d] per q/k/v section.
// ============================================================================
__global__ void __launch_bounds__(256) qkv_gemm(const float* __restrict__ x,
                                                const float* __restrict__ xlo,
                                                const float* __restrict__ xhi,
                                                const float* __restrict__ W) {
    __shared__ float sX[16][68], sM[16][68], sR[16][68], sW[16][68], sA[16][68];
    const int tid = threadIdx.x;
    const int tx = tid & 15, ty = tid >> 4;
    const int n0 = blockIdx.x * 64, m0 = blockIdx.y * 64;
    const int lr = tid >> 2, lc = tid & 3;

    const float* px = x   + (m0 + lr) * 768 + lc * 4;
    const float* pl = xlo + (m0 + lr) * 768 + lc * 4;
    const float* pu = xhi + (m0 + lr) * 768 + lc * 4;
    const float* pw = W   + (n0 + lr) * 768 + lc * 4;

    float an[4][4], am[4][4], ar[4][4];
#pragma unroll
    for (int i = 0; i < 4; i++)
#pragma unroll
        for (int j = 0; j < 4; j++) { an[i][j] = 0.f; am[i][j] = 0.f; ar[i][j] = 0.f; }

    float4 rx = *(const float4*)px;
    float4 rl = *(const float4*)pl;
    float4 ru = *(const float4*)pu;
    float4 rw = *(const float4*)pw;

    for (int kt = 0; kt < 48; kt++) {
        {
            const int kc = lc * 4;
            st4(sX, kc, lr, rx);
            float4 md = make_float4(0.5f * (rl.x + ru.x), 0.5f * (rl.y + ru.y),
                                    0.5f * (rl.z + ru.z), 0.5f * (rl.w + ru.w));
            float4 rd = make_float4(0.5f * (ru.x - rl.x), 0.5f * (ru.y - rl.y),
                                    0.5f * (ru.z - rl.z), 0.5f * (ru.w - rl.w));
            st4(sM, kc, lr, md);
            st4(sR, kc, lr, rd);
            st4(sW, kc, lr, rw);
            float4 aw = make_float4(fabsf(rw.x), fabsf(rw.y), fabsf(rw.z), fabsf(rw.w));
            st4(sA, kc, lr, aw);
        }
        __syncthreads();
        if (kt < 47) {
            const int off = (kt + 1) * 16;
            rx = *(const float4*)(px + off);
            rl = *(const float4*)(pl + off);
            ru = *(const float4*)(pu + off);
            rw = *(const float4*)(pw + off);
        }
#pragma unroll
        for (int kk = 0; kk < 16; kk++) {
            float4 fa = *(const float4*)&sX[kk][ty * 4];
            float4 fm = *(const float4*)&sM[kk][ty * 4];
            float4 fr = *(const float4*)&sR[kk][ty * 4];
            float4 fw = *(const float4*)&sW[kk][tx * 4];
            float4 fb = *(const float4*)&sA[kk][tx * 4];
            float a_[4] = {fa.x, fa.y, fa.z, fa.w};
            float m_[4] = {fm.x, fm.y, fm.z, fm.w};
            float r_[4] = {fr.x, fr.y, fr.z, fr.w};
            float w_[4] = {fw.x, fw.y, fw.z, fw.w};
            float b_[4] = {fb.x, fb.y, fb.z, fb.w};
#pragma unroll
            for (int i = 0; i < 4; i++)
#pragma unroll
                for (int j = 0; j < 4; j++) {
                    an[i][j] += a_[i] * w_[j];
                    am[i][j] += m_[i] * w_[j];
                    ar[i][j] += r_[i] * b_[j];
                }
        }
        __syncthreads();
    }

    // Epilogue: n0 is 64-aligned so tile = one (sec, head); m tile = one b.
    const int sec = n0 / 768;
    const int h   = (n0 % 768) >> 6;
    const int b   = m0 >> 11;
    const int t0  = (m0 & 2047) + ty * 4;
    const int dd  = tx * 4;
    float* pn  = g_qkv + sec * TSZ       + (b * 12 + h) * HSTRIDE;
    float* plo = g_qkv + (3 + sec) * TSZ + (b * 12 + h) * HSTRIDE;
    float* phi = g_qkv + (6 + sec) * TSZ + (b * 12 + h) * HSTRIDE;
#pragma unroll
    for (int i = 0; i < 4; i++) {
        const int off = (t0 + i) * 64 + dd;
        *(float4*)(pn + off) = make_float4(an[i][0], an[i][1], an[i][2], an[i][3]);
        *(float4*)(plo + off) = make_float4(am[i][0] - ar[i][0], am[i][1] - ar[i][1],
                                            am[i][2] - ar[i][2], am[i][3] - ar[i][3]);
        *(float4*)(phi + off) = make_float4(am[i][0] + ar[i][0], am[i][1] + ar[i][1],
                                            am[i][2] + ar[i][2], am[i][3] + ar[i][3]);
    }
}

// ============================================================================
// Kernel 2: causal flash attention, fp32 with packed f32x2 FMAs.
// Grid: (T/128, B*H, 9). z=0 nominal; z=1..8 the 8 lo/hi combos (q=c>>2, k=(c>>1)&1, v=c&1).
// Block: 128 threads, one query row per thread, D=64 in packed registers.
// Key tiles of 32, two-pass per tile (scores -> tile max -> single rescale -> PV).
// ============================================================================
__global__ void __launch_bounds__(128, 3) attn_kernel() {
    __shared__ ulonglong2 sK[32][16];
    __shared__ ulonglong2 sV[32][16];
    __shared__ float sS[128 * 33];

    const int tid = threadIdx.x;
    const int qt  = blockIdx.x;
    const int bh  = blockIdx.y;
    const int z   = blockIdx.z;

    const float *Q, *K, *V;
    float* O;
    if (z == 0) {
        Q = g_qkv;  K = g_qkv + TSZ;  V = g_qkv + 2 * TSZ;  O = g_att + 8 * TSZ;
    } else {
        const int c = z - 1;
        Q = g_qkv + (3 + 3 * ((c >> 2) & 1)) * TSZ;
        K = g_qkv + (3 + 3 * ((c >> 1) & 1) + 1) * TSZ;
        V = g_qkv + (3 + 3 * (c & 1) + 2) * TSZ;
        O = g_att + c * TSZ;
    }
    const int base = bh * HSTRIDE;
    Q += base; K += base; V += base; O += base;

    const int qi = qt * 128 + tid;

    // Load q row, pre-scaled by 1/sqrt(D)=0.125, packed f32x2.
    u64 q2[32];
    {
        const float4* qr = (const float4*)(Q + qi * 64);
#pragma unroll
        for (int i = 0; i < 16; i++) {
            float4 v = qr[i];
            q2[2 * i]     = pk2(v.x * 0.125f, v.y * 0.125f);
            q2[2 * i + 1] = pk2(v.z * 0.125f, v.w * 0.125f);
        }
    }
    u64 acc2[32];
#pragma unroll
    for (int i = 0; i < 32; i++) acc2[i] = 0ull;
    float mrun = -INFINITY, lrun = 0.f;

    const int ntiles = (qt + 1) * 4;   // keys up to qt*128+127
    for (int kt = 0; kt < ntiles; kt++) {
        __syncthreads();
        {   // cooperative K/V tile load: 32 keys x 64 floats each, contiguous
            const float4* kg = (const float4*)(K + kt * 2048);
            const float4* vg = (const float4*)(V + kt * 2048);
            float4* sk = (float4*)sK;
            float4* sv = (float4*)sV;
#pragma unroll
            for (int i = 0; i < 4; i++) {
                sk[tid + 128 * i] = kg[tid + 128 * i];
                sv[tid + 128 * i] = vg[tid + 128 * i];
            }
        }
        __syncthreads();

        const int kbase = kt * 32;
        if (kbase <= qi) {      // tile has at least one unmasked key for this query
            // Pass 1: scores for 32 keys
            float smax = -INFINITY;
#pragma unroll 2
            for (int j = 0; j < 32; j++) {
                u64 sa = 0ull, sb = 0ull;
                const ulonglong2* kr = &sK[j][0];
#pragma unroll
                for (int d = 0; d < 16; d++) {
                    ulonglong2 kk = kr[d];
                    sa = fma2(q2[2 * d],     kk.x, sa);
                    sb = fma2(q2[2 * d + 1], kk.y, sb);
                }
                float2 fa = upk2(sa), fb = upk2(sb);
                float s = (fa.x + fa.y) + (fb.x + fb.y);
                if (kbase + j > qi) s = -INFINITY;
                sS[tid * 33 + j] = s;
                smax = fmaxf(smax, s);
            }
            const float mnew = fmaxf(mrun, smax);
            const float corr = __expf(mrun - mnew);   // first tile: exp(-inf)=0
            lrun *= corr;
            const u64 c2 = pk2(corr, corr);
#pragma unroll
            for (int i = 0; i < 32; i++) acc2[i] = mul2(acc2[i], c2);
            // Pass 2: exp + PV
#pragma unroll 2
            for (int j = 0; j < 32; j++) {
                const float p = __expf(sS[tid * 33 + j] - mnew);
                lrun += p;
                const u64 p2 = pk2(p, p);
                const ulonglong2* vr = &sV[j][0];
#pragma unroll
                for (int d = 0; d < 16; d++) {
                    ulonglong2 vv = vr[d];
                    acc2[2 * d]     = fma2(p2, vv.x, acc2[2 * d]);
                    acc2[2 * d + 1] = fma2(p2, vv.y, acc2[2 * d + 1]);
                }
            }
            mrun = mnew;
        }
    }

    const float inv = 1.0f / lrun;
    float4* orow = (float4*)(O + qi * 64);
#pragma unroll
    for (int i = 0; i < 16; i++) {
        float2 a = upk2(acc2[2 * i]);
        float2 b2 = upk2(acc2[2 * i + 1]);
        orow[i] = make_float4(a.x * inv, a.y * inv, b2.x * inv, b2.y * inv);
    }
}

// ============================================================================
// Kernel 3: elementwise min/max over the 8 interval combos.
// ============================================================================
__global__ void __launch_bounds__(256) reduce_kernel() {
    const int i = blockIdx.x * 256 + threadIdx.x;   // over TSZ/4 float4s
    float4 lo = ((const float4*)g_att)[i];
    float4 hi = lo;
#pragma unroll
    for (int c = 1; c < 8; c++) {
        float4 v = ((const float4*)(g_att + c * TSZ))[i];
        lo.x = fminf(lo.x, v.x); lo.y = fminf(lo.y, v.y);
        lo.z = fminf(lo.z, v.z); lo.w = fminf(lo.w, v.w);
        hi.x = fmaxf(hi.x, v.x); hi.y = fmaxf(hi.y, v.y);
        hi.z = fmaxf(hi.z, v.z); hi.w = fmaxf(hi.w, v.w);
    }
    ((float4*)g_red)[i] = lo;
    ((float4*)(g_red + TSZ))[i] = hi;
}

// ============================================================================
// Kernel 4: fused output projection for (y, y_lo, y_hi).
// A matrices read directly from head layout (merge fused into the load),
// shared W_proj tile, 3 accumulator sets. M=4096, N=768, K=768.
// ============================================================================
__global__ void __launch_bounds__(256) proj_gemm(const float* __restrict__ W,
                                                 float* __restrict__ out) {
    __shared__ float s0[16][68], s1[16][68], s2[16][68], sW[16][68];
    const int tid = threadIdx.x;
    const int tx = tid & 15, ty = tid >> 4;
    const int n0 = blockIdx.x * 64, m0 = blockIdx.y * 64;
    const int lr = tid >> 2, lc = tid & 3;

    const float* A0 = g_att + 8 * TSZ;   // nominal
    const float* A1 = g_red;             // lo
    const float* A2 = g_red + TSZ;       // hi

    const int m = m0 + lr;
    const int b = m >> 11;
    const int t = m & 2047;
    const int rowbase = b * (12 * HSTRIDE) + t * 64;   // + h*HSTRIDE + d
    const int k0 = lc * 4;
    const float* pw = W + (n0 + lr) * 768 + k0;

    float a0[4][4], a1[4][4], a2[4][4];
#pragma unroll
    for (int i = 0; i < 4; i++)
#pragma unroll
        for (int j = 0; j < 4; j++) { a0[i][j] = 0.f; a1[i][j] = 0.f; a2[i][j] = 0.f; }

    int k = k0;                 // kt=0
    int ha = rowbase + (k >> 6) * HSTRIDE + (k & 63);
    float4 r0 = *(const float4*)(A0 + ha);
    float4 r1 = *(const float4*)(A1 + ha);
    float4 r2 = *(const float4*)(A2 + ha);
    float4 rw = *(const float4*)pw;

    for (int kt = 0; kt < 48; kt++) {
        {
            const int kc = lc * 4;
            st4(s0, kc, lr, r0);
            st4(s1, kc, lr, r1);
            st4(s2, kc, lr, r2);
            st4(sW, kc, lr, rw);
        }
        __syncthreads();
        if (kt < 47) {
            k = (kt + 1) * 16 + k0;
            ha = rowbase + (k >> 6) * HSTRIDE + (k & 63);
            r0 = *(const float4*)(A0 + ha);
            r1 = *(const float4*)(A1 + ha);
            r2 = *(const float4*)(A2 + ha);
            rw = *(const float4*)(pw + (kt + 1) * 16);
        }
#pragma unroll
        for (int kk = 0; kk < 16; kk++) {
            float4 f0 = *(const float4*)&s0[kk][ty * 4];
            float4 f1 = *(const float4*)&s1[kk][ty * 4];
            float4 f2 = *(const float4*)&s2[kk][ty * 4];
            float4 fw = *(const float4*)&sW[kk][tx * 4];
            float x0[4] = {f0.x, f0.y, f0.z, f0.w};
            float x1[4] = {f1.x, f1.y, f1.z, f1.w};
            float x2[4] = {f2.x, f2.y, f2.z, f2.w};
            float w_[4] = {fw.x, fw.y, fw.z, fw.w};
#pragma unroll
            for (int i = 0; i < 4; i++)
#pragma unroll
                for (int j = 0; j < 4; j++) {
                    a0[i][j] += x0[i] * w_[j];
                    a1[i][j] += x1[i] * w_[j];
                    a2[i][j] += x2[i] * w_[j];
                }
        }
        __syncthreads();
    }

    const int mr = m0 + ty * 4;
    const int nc = n0 + tx * 4;
#pragma unroll
    for (int i = 0; i < 4; i++) {
        float* po = out + (mr + i) * 768 + nc;
        *(float4*)(po)           = make_float4(a0[i][0], a0[i][1], a0[i][2], a0[i][3]);
        *(float4*)(po + TSZ)     = make_float4(a1[i][0], a1[i][1], a1[i][2], a1[i][3]);
        *(float4*)(po + 2 * TSZ) = make_float4(a2[i][0], a2[i][1], a2[i][2], a2[i][3]);
    }
}

extern "C" void kernel_launch(void* const* d_in, const int* in_sizes, int n_in,
                              void* d_out, int out_size) {
    const float* x  = (const float*)d_in[0];
    const float* xl = (const float*)d_in[1];
    const float* xu = (const float*)d_in[2];
    const float* Wa = (const float*)d_in[3];
    const float* Wp = (const float*)d_in[4];
    float* out = (float*)d_out;

    qkv_gemm<<<dim3(36, 64), 256>>>(x, xl, xu, Wa);       // N=2304/64, M=4096/64
    attn_kernel<<<dim3(16, 24, 9), 128>>>();              // qtiles, B*H, 9 variants
    reduce_kernel<<<TSZ / 4 / 256, 256>>>();              // 3072 blocks
    proj_gemm<<<dim3(12, 64), 256>>>(Wp, out);            // N=768/64, M=4096/64
}

// round 2
// speedup vs baseline: 2.6371x; 2.6371x over previous
#include <cuda_runtime.h>
#include <cstdint>

// Problem constants
#define TB 2
#define TT 2048
#define TC 768
#define TH 12
#define TD 64
#define TM 4096              // B*T
#define TSZ 3145728          // B*T*C = per-tensor element count
#define HSTRIDE 131072       // T*D = 2048*64

__device__ float g_qkv[9 * TSZ];
__device__ float g_att[9 * TSZ];
__device__ float g_red[2 * TSZ];

__device__ __forceinline__ void st4(float (*sm)[68], int kc, int lr, float4 v) {
    sm[kc + 0][lr] = v.x; sm[kc + 1][lr] = v.y;
    sm[kc + 2][lr] = v.z; sm[kc + 3][lr] = v.w;
}

__device__ __forceinline__ uint32_t f2tf32(float x) {
    uint32_t t; asm("cvt.rna.tf32.f32 %0,%1;" : "=r"(t) : "f"(x)); return t;
}

__device__ __forceinline__ void mma_tf32(float& d0, float& d1, float& d2, float& d3,
                                         uint32_t a0, uint32_t a1, uint32_t a2, uint32_t a3,
                                         uint32_t b0, uint32_t b1) {
    asm volatile("mma.sync.aligned.m16n8k8.row.col.f32.tf32.tf32.f32 "
                 "{%0,%1,%2,%3},{%4,%5,%6,%7},{%8,%9},{%0,%1,%2,%3};"
                 : "+f"(d0), "+f"(d1), "+f"(d2), "+f"(d3)
                 : "r"(a0), "r"(a1), "r"(a2), "r"(a3), "r"(b0), "r"(b1));
}

// ============================================================================
// Kernel 1: fused QKV GEMM (unchanged from R1).
// ============================================================================
__global__ void __launch_bounds__(256) qkv_gemm(const float* __restrict__ x,
                                                const float* __restrict__ xlo,
                                                const float* __restrict__ xhi,
                                                const float* __restrict__ W) {
    __shared__ float sX[16][68], sM[16][68], sR[16][68], sW[16][68], sA[16][68];
    const int tid = threadIdx.x;
    const int tx = tid & 15, ty = tid >> 4;
    const int n0 = blockIdx.x * 64, m0 = blockIdx.y * 64;
    const int lr = tid >> 2, lc = tid & 3;

    const float* px = x   + (m0 + lr) * 768 + lc * 4;
    const float* pl = xlo + (m0 + lr) * 768 + lc * 4;
    const float* pu = xhi + (m0 + lr) * 768 + lc * 4;
    const float* pw = W   + (n0 + lr) * 768 + lc * 4;

    float an[4][4], am[4][4], ar[4][4];
#pragma unroll
    for (int i = 0; i < 4; i++)
#pragma unroll
        for (int j = 0; j < 4; j++) { an[i][j] = 0.f; am[i][j] = 0.f; ar[i][j] = 0.f; }

    float4 rx = *(const float4*)px;
    float4 rl = *(const float4*)pl;
    float4 ru = *(const float4*)pu;
    float4 rw = *(const float4*)pw;

    for (int kt = 0; kt < 48; kt++) {
        {
            const int kc = lc * 4;
            st4(sX, kc, lr, rx);
            float4 md = make_float4(0.5f * (rl.x + ru.x), 0.5f * (rl.y + ru.y),
                                    0.5f * (rl.z + ru.z), 0.5f * (rl.w + ru.w));
            float4 rd = make_float4(0.5f * (ru.x - rl.x), 0.5f * (ru.y - rl.y),
                                    0.5f * (ru.z - rl.z), 0.5f * (ru.w - rl.w));
            st4(sM, kc, lr, md);
            st4(sR, kc, lr, rd);
            st4(sW, kc, lr, rw);
            float4 aw = make_float4(fabsf(rw.x), fabsf(rw.y), fabsf(rw.z), fabsf(rw.w));
            st4(sA, kc, lr, aw);
        }
        __syncthreads();
        if (kt < 47) {
            const int off = (kt + 1) * 16;
            rx = *(const float4*)(px + off);
            rl = *(const float4*)(pl + off);
            ru = *(const float4*)(pu + off);
            rw = *(const float4*)(pw + off);
        }
#pragma unroll
        for (int kk = 0; kk < 16; kk++) {
            float4 fa = *(const float4*)&sX[kk][ty * 4];
            float4 fm = *(const float4*)&sM[kk][ty * 4];
            float4 fr = *(const float4*)&sR[kk][ty * 4];
            float4 fw = *(const float4*)&sW[kk][tx * 4];
            float4 fb = *(const float4*)&sA[kk][tx * 4];
            float a_[4] = {fa.x, fa.y, fa.z, fa.w};
            float m_[4] = {fm.x, fm.y, fm.z, fm.w};
            float r_[4] = {fr.x, fr.y, fr.z, fr.w};
            float w_[4] = {fw.x, fw.y, fw.z, fw.w};
            float b_[4] = {fb.x, fb.y, fb.z, fb.w};
#pragma unroll
            for (int i = 0; i < 4; i++)
#pragma unroll
                for (int j = 0; j < 4; j++) {
                    an[i][j] += a_[i] * w_[j];
                    am[i][j] += m_[i] * w_[j];
                    ar[i][j] += r_[i] * b_[j];
                }
        }
        __syncthreads();
    }

    const int sec = n0 / 768;
    const int h   = (n0 % 768) >> 6;
    const int b   = m0 >> 11;
    const int t0  = (m0 & 2047) + ty * 4;
    const int dd  = tx * 4;
    float* pn  = g_qkv + sec * TSZ       + (b * 12 + h) * HSTRIDE;
    float* plo = g_qkv + (3 + sec) * TSZ + (b * 12 + h) * HSTRIDE;
    float* phi = g_qkv + (6 + sec) * TSZ + (b * 12 + h) * HSTRIDE;
#pragma unroll
    for (int i = 0; i < 4; i++) {
        const int off = (t0 + i) * 64 + dd;
        *(float4*)(pn + off) = make_float4(an[i][0], an[i][1], an[i][2], an[i][3]);
        *(float4*)(plo + off) = make_float4(am[i][0] - ar[i][0], am[i][1] - ar[i][1],
                                            am[i][2] - ar[i][2], am[i][3] - ar[i][3]);
        *(float4*)(phi + off) = make_float4(am[i][0] + ar[i][0], am[i][1] + ar[i][1],
                                            am[i][2] + ar[i][2], am[i][3] + ar[i][3]);
    }
}

// ============================================================================
// Kernel 2: causal flash attention with TF32 mma.sync (m16n8k8).
// Grid (T/128, B*H, 9). Block 256 threads = 8 warps; warp w owns 16 query rows.
// Key tiles of 32. K/V staged in smem in B-fragment layout (tf32 bits) so each
// warp fetches mma operands with conflict-free LDS.64. P goes through a small
// per-warp swizzled smem buffer to convert D-fragment -> A-fragment layout.
// ============================================================================
__global__ void __launch_bounds__(256, 2) attn_mma() {
    // K frags: [kf(d) 0..7][nf(key) 0..3][lane*2+reg], kf stride padded to 268
    __shared__ uint32_t sKf[8 * 268];
    // V frags: [kf(key) 0..3][nf(d) 0..7][lane*2+reg]
    __shared__ uint32_t sVf[32 * 64];
    // P buffer: per warp 16 rows x 32 cols, col rotated by 8*(row&7)
    __shared__ uint32_t sP[8 * 512];

    const int tid  = threadIdx.x;
    const int w    = tid >> 5;
    const int lane = tid & 31;
    const int g    = lane >> 2;
    const int tig  = lane & 3;

    const int qt = blockIdx.x;
    const int bh = blockIdx.y;
    const int z  = blockIdx.z;

    const float *Q, *K, *V;
    float* O;
    if (z == 0) {
        Q = g_qkv;  K = g_qkv + TSZ;  V = g_qkv + 2 * TSZ;  O = g_att + 8 * TSZ;
    } else {
        const int c = z - 1;
        Q = g_qkv + (3 + 3 * ((c >> 2) & 1)) * TSZ;
        K = g_qkv + (3 + 3 * ((c >> 1) & 1) + 1) * TSZ;
        V = g_qkv + (3 + 3 * (c & 1) + 2) * TSZ;
        O = g_att + c * TSZ;
    }
    const int base = bh * HSTRIDE;
    Q += base; K += base; V += base; O += base;

    const int q0   = qt * 128;
    const int q_lo = q0 + w * 16;       // warp's first query row
    const int q_hi = q_lo + 15;

    // ---- Q A-fragments (tf32), pre-scaled by 1/sqrt(64) ----
    uint32_t qa[8][4];
    {
        const float* rA = Q + (q_lo + g) * 64;
        const float* rB = Q + (q_lo + g + 8) * 64;
#pragma unroll
        for (int kf = 0; kf < 8; kf++) {
            qa[kf][0] = f2tf32(rA[kf * 8 + tig] * 0.125f);
            qa[kf][1] = f2tf32(rB[kf * 8 + tig] * 0.125f);
            qa[kf][2] = f2tf32(rA[kf * 8 + tig + 4] * 0.125f);
            qa[kf][3] = f2tf32(rB[kf * 8 + tig + 4] * 0.125f);
        }
    }

    float o[8][4];
#pragma unroll
    for (int nf = 0; nf < 8; nf++)
#pragma unroll
        for (int r = 0; r < 4; r++) o[nf][r] = 0.f;
    float m0 = -1e30f, m1 = -1e30f, l0 = 0.f, l1 = 0.f;

    // V loader constants (thread -> 8 coalesced LDG.32, one STS.128 pair)
    const int vkf = tid >> 6;            // key block 0..3
    const int vnf = (tid >> 3) & 7;      // d block 0..7
    const int vg  = tid & 7;             // d within block
    const int vbase = (vkf * 8 + vnf) * 64 + vg * 8;

    const int ntiles = qt * 4 + 4;       // keys up to q0+127

    for (int kt = 0; kt < ntiles; kt++) {
        const int kbase = kt * 32;
        __syncthreads();
        // ---- cooperative K tile -> frag smem ----
        {
            const float4* kg = (const float4*)(K + kbase * 64);
#pragma unroll
            for (int i = 0; i < 2; i++) {
                const int idx = tid + 256 * i;
                const int key = idx >> 4;
                const int d0  = (idx & 15) * 4;
                float4 v = kg[idx];
                const int kf  = d0 >> 3;
                const int rg  = (d0 >> 2) & 1;
                const int b_  = kf * 268 + (key >> 3) * 64 + (key & 7) * 8 + rg;
                sKf[b_ + 0] = f2tf32(v.x);
                sKf[b_ + 2] = f2tf32(v.y);
                sKf[b_ + 4] = f2tf32(v.z);
                sKf[b_ + 6] = f2tf32(v.w);
            }
        }
        // ---- cooperative V tile -> frag smem ----
        {
            const float* vt = V + kbase * 64;
            uint32_t tmp[8];
#pragma unroll
            for (int j = 0; j < 8; j++) {
                const int key = vkf * 8 + (j & 1) * 4 + (j >> 1);
                tmp[j] = f2tf32(vt[key * 64 + vnf * 8 + vg]);
            }
            *(uint4*)&sVf[vbase]     = make_uint4(tmp[0], tmp[1], tmp[2], tmp[3]);
            *(uint4*)&sVf[vbase + 4] = make_uint4(tmp[4], tmp[5], tmp[6], tmp[7]);
        }
        __syncthreads();

        if (kbase > q_hi) continue;      // warp-uniform

        // ---- S = Q @ K^T  (16 x 32) ----
        float dS[4][4];
#pragma unroll
        for (int nf = 0; nf < 4; nf++)
#pragma unroll
            for (int r = 0; r < 4; r++) dS[nf][r] = 0.f;
#pragma unroll
        for (int kf = 0; kf < 8; kf++) {
#pragma unroll
            for (int nf = 0; nf < 4; nf++) {
                uint2 kb = *(const uint2*)&sKf[kf * 268 + nf * 64 + lane * 2];
                mma_tf32(dS[nf][0], dS[nf][1], dS[nf][2], dS[nf][3],
                         qa[kf][0], qa[kf][1], qa[kf][2], qa[kf][3], kb.x, kb.y);
            }
        }

        // ---- causal mask (only boundary tiles) ----
        if (kbase + 31 > q_lo) {
            const int rowA = q_lo + g, rowB = rowA + 8;
#pragma unroll
            for (int nf = 0; nf < 4; nf++) {
                const int key0 = kbase + nf * 8 + 2 * tig;
                if (key0 > rowA)     dS[nf][0] = -1e30f;
                if (key0 + 1 > rowA) dS[nf][1] = -1e30f;
                if (key0 > rowB)     dS[nf][2] = -1e30f;
                if (key0 + 1 > rowB) dS[nf][3] = -1e30f;
            }
        }

        // ---- online softmax ----
        float mt0 = -1e30f, mt1 = -1e30f;
#pragma unroll
        for (int nf = 0; nf < 4; nf++) {
            mt0 = fmaxf(mt0, fmaxf(dS[nf][0], dS[nf][1]));
            mt1 = fmaxf(mt1, fmaxf(dS[nf][2], dS[nf][3]));
        }
        mt0 = fmaxf(mt0, __shfl_xor_sync(0xffffffffu, mt0, 1));
        mt1 = fmaxf(mt1, __shfl_xor_sync(0xffffffffu, mt1, 1));
        mt0 = fmaxf(mt0, __shfl_xor_sync(0xffffffffu, mt0, 2));
        mt1 = fmaxf(mt1, __shfl_xor_sync(0xffffffffu, mt1, 2));

        const float mn0 = fmaxf(m0, mt0), mn1 = fmaxf(m1, mt1);
        const float c0 = __expf(m0 - mn0), c1 = __expf(m1 - mn1);
        m0 = mn0; m1 = mn1;
        l0 *= c0;  l1 *= c1;
#pragma unroll
        for (int nf = 0; nf < 8; nf++) {
            o[nf][0] *= c0; o[nf][1] *= c0;
            o[nf][2] *= c1; o[nf][3] *= c1;
        }

        // ---- p = exp(s - m), stash to swizzled P smem as tf32 ----
        const int pw0 = w * 512 + g * 32;
        const int rot = (g * 8);
#pragma unroll
        for (int nf = 0; nf < 4; nf++) {
            float p0 = __expf(dS[nf][0] - mn0);
            float p1 = __expf(dS[nf][1] - mn0);
            float p2 = __expf(dS[nf][2] - mn1);
            float p3 = __expf(dS[nf][3] - mn1);
            l0 += p0 + p1;
            l1 += p2 + p3;
            const int colr = (nf * 8 + tig * 2 + rot) & 31;
            *(uint2*)&sP[pw0 + colr]       = make_uint2(f2tf32(p0), f2tf32(p1));
            *(uint2*)&sP[pw0 + 256 + colr] = make_uint2(f2tf32(p2), f2tf32(p3));
        }
        __syncwarp();

        // ---- reload P as A-fragments ----
        uint32_t pa[4][4];
#pragma unroll
        for (int kf = 0; kf < 4; kf++) {
            pa[kf][0] = sP[pw0 +       ((kf * 8 + tig + rot) & 31)];
            pa[kf][1] = sP[pw0 + 256 + ((kf * 8 + tig + rot) & 31)];
            pa[kf][2] = sP[pw0 +       ((kf * 8 + tig + 4 + rot) & 31)];
            pa[kf][3] = sP[pw0 + 256 + ((kf * 8 + tig + 4 + rot) & 31)];
        }

        // ---- O += P @ V ----
#pragma unroll
        for (int kf = 0; kf < 4; kf++) {
#pragma unroll
            for (int nf = 0; nf < 8; nf++) {
                uint2 vb = *(const uint2*)&sVf[(kf * 8 + nf) * 64 + lane * 2];
                mma_tf32(o[nf][0], o[nf][1], o[nf][2], o[nf][3],
                         pa[kf][0], pa[kf][1], pa[kf][2], pa[kf][3], vb.x, vb.y);
            }
        }
    }

    // ---- epilogue ----
    l0 += __shfl_xor_sync(0xffffffffu, l0, 1);
    l1 += __shfl_xor_sync(0xffffffffu, l1, 1);
    l0 += __shfl_xor_sync(0xffffffffu, l0, 2);
    l1 += __shfl_xor_sync(0xffffffffu, l1, 2);
    const float i0 = 1.0f / l0, i1 = 1.0f / l1;

    float* oA = O + (q_lo + g) * 64;
    float* oB = O + (q_lo + g + 8) * 64;
#pragma unroll
    for (int nf = 0; nf < 8; nf++) {
        *(float2*)&oA[nf * 8 + tig * 2] = make_float2(o[nf][0] * i0, o[nf][1] * i0);
        *(float2*)&oB[nf * 8 + tig * 2] = make_float2(o[nf][2] * i1, o[nf][3] * i1);
    }
}

// ============================================================================
// Kernel 3: elementwise min/max over the 8 interval combos (unchanged).
// ============================================================================
__global__ void __launch_bounds__(256) reduce_kernel() {
    const int i = blockIdx.x * 256 + threadIdx.x;
    float4 lo = ((const float4*)g_att)[i];
    float4 hi = lo;
#pragma unroll
    for (int c = 1; c < 8; c++) {
        float4 v = ((const float4*)(g_att + c * TSZ))[i];
        lo.x = fminf(lo.x, v.x); lo.y = fminf(lo.y, v.y);
        lo.z = fminf(lo.z, v.z); lo.w = fminf(lo.w, v.w);
        hi.x = fmaxf(hi.x, v.x); hi.y = fmaxf(hi.y, v.y);
        hi.z = fmaxf(hi.z, v.z); hi.w = fmaxf(hi.w, v.w);
    }
    ((float4*)g_red)[i] = lo;
    ((float4*)(g_red + TSZ))[i] = hi;
}

// ============================================================================
// Kernel 4: fused output projection for (y, y_lo, y_hi) (unchanged).
// ============================================================================
__global__ void __launch_bounds__(256) proj_gemm(const float* __restrict__ W,
                                                 float* __restrict__ out) {
    __shared__ float s0[16][68], s1[16][68], s2[16][68], sW[16][68];
    const int tid = threadIdx.x;
    const int tx = tid & 15, ty = tid >> 4;
    const int n0 = blockIdx.x * 64, m0 = blockIdx.y * 64;
    const int lr = tid >> 2, lc = tid & 3;

    const float* A0 = g_att + 8 * TSZ;
    const float* A1 = g_red;
    const float* A2 = g_red + TSZ;

    const int m = m0 + lr;
    const int b = m >> 11;
    const int t = m & 2047;
    const int rowbase = b * (12 * HSTRIDE) + t * 64;
    const int k0 = lc * 4;
    const float* pw = W + (n0 + lr) * 768 + k0;

    float a0[4][4], a1[4][4], a2[4][4];
#pragma unroll
    for (int i = 0; i < 4; i++)
#pragma unroll
        for (int j = 0; j < 4; j++) { a0[i][j] = 0.f; a1[i][j] = 0.f; a2[i][j] = 0.f; }

    int k = k0;
    int ha = rowbase + (k >> 6) * HSTRIDE + (k & 63);
    float4 r0 = *(const float4*)(A0 + ha);
    float4 r1 = *(const float4*)(A1 + ha);
    float4 r2 = *(const float4*)(A2 + ha);
    float4 rw = *(const float4*)pw;

    for (int kt = 0; kt < 48; kt++) {
        {
            const int kc = lc * 4;
            st4(s0, kc, lr, r0);
            st4(s1, kc, lr, r1);
            st4(s2, kc, lr, r2);
            st4(sW, kc, lr, rw);
        }
        __syncthreads();
        if (kt < 47) {
            k = (kt + 1) * 16 + k0;
            ha = rowbase + (k >> 6) * HSTRIDE + (k & 63);
            r0 = *(const float4*)(A0 + ha);
            r1 = *(const float4*)(A1 + ha);
            r2 = *(const float4*)(A2 + ha);
            rw = *(const float4*)(pw + (kt + 1) * 16);
        }
#pragma unroll
        for (int kk = 0; kk < 16; kk++) {
            float4 f0 = *(const float4*)&s0[kk][ty * 4];
            float4 f1 = *(const float4*)&s1[kk][ty * 4];
            float4 f2 = *(const float4*)&s2[kk][ty * 4];
            float4 fw = *(const float4*)&sW[kk][tx * 4];
            float x0[4] = {f0.x, f0.y, f0.z, f0.w};
            float x1[4] = {f1.x, f1.y, f1.z, f1.w};
            float x2[4] = {f2.x, f2.y, f2.z, f2.w};
            float w_[4] = {fw.x, fw.y, fw.z, fw.w};
#pragma unroll
            for (int i = 0; i < 4; i++)
#pragma unroll
                for (int j = 0; j < 4; j++) {
                    a0[i][j] += x0[i] * w_[j];
                    a1[i][j] += x1[i] * w_[j];
                    a2[i][j] += x2[i] * w_[j];
                }
        }
        __syncthreads();
    }

    const int mr = m0 + ty * 4;
    const int nc = n0 + tx * 4;
#pragma unroll
    for (int i = 0; i < 4; i++) {
        float* po = out + (mr + i) * 768 + nc;
        *(float4*)(po)           = make_float4(a0[i][0], a0[i][1], a0[i][2], a0[i][3]);
        *(float4*)(po + TSZ)     = make_float4(a1[i][0], a1[i][1], a1[i][2], a1[i][3]);
        *(float4*)(po + 2 * TSZ) = make_float4(a2[i][0], a2[i][1], a2[i][2], a2[i][3]);
    }
}

extern "C" void kernel_launch(void* const* d_in, const int* in_sizes, int n_in,
                              void* d_out, int out_size) {
    const float* x  = (const float*)d_in[0];
    const float* xl = (const float*)d_in[1];
    const float* xu = (const float*)d_in[2];
    const float* Wa = (const float*)d_in[3];
    const float* Wp = (const float*)d_in[4];
    float* out = (float*)d_out;

    qkv_gemm<<<dim3(36, 64), 256>>>(x, xl, xu, Wa);
    attn_mma<<<dim3(16, 24, 9), 256>>>();
    reduce_kernel<<<TSZ / 4 / 256, 256>>>();
    proj_gemm<<<dim3(12, 64), 256>>>(Wp, out);
}

// round 3
// speedup vs baseline: 3.8754x; 1.4696x over previous
#include <cuda_runtime.h>
#include <cstdint>

// Problem constants
#define TB 2
#define TT 2048
#define TC 768
#define TH 12
#define TD 64
#define TM 4096              // B*T
#define TSZ 3145728          // B*T*C
#define HSTRIDE 131072       // T*D

__device__ float g_qkv[9 * TSZ];
__device__ float g_att[9 * TSZ];
__device__ float g_red[2 * TSZ];

__device__ __forceinline__ uint32_t f2tf32(float x) {
    uint32_t t; asm("cvt.rna.tf32.f32 %0,%1;" : "=r"(t) : "f"(x)); return t;
}

__device__ __forceinline__ void mma_tf32(float& d0, float& d1, float& d2, float& d3,
                                         uint32_t a0, uint32_t a1, uint32_t a2, uint32_t a3,
                                         uint32_t b0, uint32_t b1) {
    asm volatile("mma.sync.aligned.m16n8k8.row.col.f32.tf32.tf32.f32 "
                 "{%0,%1,%2,%3},{%4,%5,%6,%7},{%8,%9},{%0,%1,%2,%3};"
                 : "+f"(d0), "+f"(d1), "+f"(d2), "+f"(d3)
                 : "r"(a0), "r"(a1), "r"(a2), "r"(a3), "r"(b0), "r"(b1));
}

__device__ __forceinline__ uint4 cvt4(float4 v) {
    return make_uint4(f2tf32(v.x), f2tf32(v.y), f2tf32(v.z), f2tf32(v.w));
}

// A-frag smem store: tile 128 rows x 16 k, layout [mf*2+kfl][reg][lane(32)],
// lane-group XOR swizzle by k-chunk c so STS.128 phases hit 8 distinct bank-groups.
__device__ __forceinline__ void stA(uint32_t* sA, int row, int lc, uint4 v) {
    const int mf  = row >> 4;
    const int kfl = lc >> 1;
    const int reg = ((lc & 1) << 1) | ((row >> 3) & 1);
    uint32_t* p = sA + ((mf * 2 + kfl) * 4 + reg) * 32 + ((((row & 7) ^ (lc << 1)) << 2));
    *(uint4*)p = v;
}
// B-frag smem store: tile 64 rows x 16 k, layout [nf*2+kf][reg(2)][lane(32)].
__device__ __forceinline__ void stB(uint32_t* sB, int nrow, int lc, uint4 v) {
    const int nf  = nrow >> 3;
    const int kfl = lc >> 1;
    const int reg = lc & 1;
    uint32_t* p = sB + ((nf * 2 + kfl) * 2 + reg) * 32 + ((((nrow & 7) ^ (lc << 1)) << 2));
    *(uint4*)p = v;
}

// ============================================================================
// Kernel 1: fused QKV GEMM, TF32 mma.
//   acc0 = x@W^T, acc1 = mid@W^T, acc2 = rad@|W|^T ; lo/hi = acc1 -/+ acc2.
// M=4096 N=2304 K=768. BM=128 BN=64 BK=16, 8 warps, warp tile 32x32, 3 acc sets.
// ============================================================================
__global__ void __launch_bounds__(256, 1) qkv_mma(const float* __restrict__ x,
                                                  const float* __restrict__ xlo,
                                                  const float* __restrict__ xhi,
                                                  const float* __restrict__ W) {
    __shared__ uint32_t sA[3 * 2048];
    __shared__ uint32_t sB[1024];

    const int tid  = threadIdx.x;
    const int lane = tid & 31;
    const int w    = tid >> 5;
    const int g    = lane >> 2, tig = lane & 3;
    const int mw   = w >> 1, nw = w & 1;
    const int n0   = blockIdx.x * 64, m0 = blockIdx.y * 128;
    const int lrow = tid >> 2;
    const int lc   = tid & 3;

    const float* px = x   + (m0 + lrow) * 768 + lc * 4;
    const float* pl = xlo + (m0 + lrow) * 768 + lc * 4;
    const float* pu = xhi + (m0 + lrow) * 768 + lc * 4;
    const float* pw = W   + (n0 + lrow) * 768 + lc * 4;

    float acc[3][2][4][4];
#pragma unroll
    for (int t = 0; t < 3; t++)
#pragma unroll
        for (int i = 0; i < 2; i++)
#pragma unroll
            for (int j = 0; j < 4; j++)
#pragma unroll
                for (int r = 0; r < 4; r++) acc[t][i][j][r] = 0.f;

    float4 vx[2], vl[2], vu[2], vw;
    vx[0] = *(const float4*)px;  vx[1] = *(const float4*)(px + 64 * 768);
    vl[0] = *(const float4*)pl;  vl[1] = *(const float4*)(pl + 64 * 768);
    vu[0] = *(const float4*)pu;  vu[1] = *(const float4*)(pu + 64 * 768);
    vw    = *(const float4*)pw;

    for (int kt = 0; kt < 48; kt++) {
        if (kt) __syncthreads();
#pragma unroll
        for (int i = 0; i < 2; i++) {
            const int row = lrow + 64 * i;
            stA(sA, row, lc, cvt4(vx[i]));
            float4 md = make_float4(0.5f * (vl[i].x + vu[i].x), 0.5f * (vl[i].y + vu[i].y),
                                    0.5f * (vl[i].z + vu[i].z), 0.5f * (vl[i].w + vu[i].w));
            float4 rd = make_float4(0.5f * (vu[i].x - vl[i].x), 0.5f * (vu[i].y - vl[i].y),
                                    0.5f * (vu[i].z - vl[i].z), 0.5f * (vu[i].w - vl[i].w));
            stA(sA + 2048, row, lc, cvt4(md));
            stA(sA + 4096, row, lc, cvt4(rd));
        }
        stB(sB, lrow, lc, cvt4(vw));
        __syncthreads();
        if (kt < 47) {
            const int off = (kt + 1) * 16;
            vx[0] = *(const float4*)(px + off); vx[1] = *(const float4*)(px + off + 64 * 768);
            vl[0] = *(const float4*)(pl + off); vl[1] = *(const float4*)(pl + off + 64 * 768);
            vu[0] = *(const float4*)(pu + off); vu[1] = *(const float4*)(pu + off + 64 * 768);
            vw    = *(const float4*)(pw + off);
        }
#pragma unroll
        for (int kf = 0; kf < 2; kf++) {
            uint32_t a[3][2][4];
#pragma unroll
            for (int t = 0; t < 3; t++)
#pragma unroll
                for (int mfi = 0; mfi < 2; mfi++) {
                    const int base = t * 2048 + ((mw * 2 + mfi) * 2 + kf) * 128;
#pragma unroll
                    for (int r = 0; r < 4; r++)
                        a[t][mfi][r] = sA[base + r * 32 + (lane ^ ((kf * 2 + (r >> 1)) << 3))];
                }
            uint32_t b[4][2], ba[4][2];
#pragma unroll
            for (int nfi = 0; nfi < 4; nfi++) {
                const int base = ((nw * 4 + nfi) * 2 + kf) * 64;
#pragma unroll
                for (int r = 0; r < 2; r++) {
                    b[nfi][r]  = sB[base + r * 32 + (lane ^ ((kf * 2 + r) << 3))];
                    ba[nfi][r] = b[nfi][r] & 0x7fffffffu;
                }
            }
#pragma unroll
            for (int mfi = 0; mfi < 2; mfi++)
#pragma unroll
                for (int nfi = 0; nfi < 4; nfi++) {
                    mma_tf32(acc[0][mfi][nfi][0], acc[0][mfi][nfi][1], acc[0][mfi][nfi][2], acc[0][mfi][nfi][3],
                             a[0][mfi][0], a[0][mfi][1], a[0][mfi][2], a[0][mfi][3], b[nfi][0], b[nfi][1]);
                    mma_tf32(acc[1][mfi][nfi][0], acc[1][mfi][nfi][1], acc[1][mfi][nfi][2], acc[1][mfi][nfi][3],
                             a[1][mfi][0], a[1][mfi][1], a[1][mfi][2], a[1][mfi][3], b[nfi][0], b[nfi][1]);
                    mma_tf32(acc[2][mfi][nfi][0], acc[2][mfi][nfi][1], acc[2][mfi][nfi][2], acc[2][mfi][nfi][3],
                             a[2][mfi][0], a[2][mfi][1], a[2][mfi][2], a[2][mfi][3], ba[nfi][0], ba[nfi][1]);
                }
        }
    }

    // Epilogue: n-tile = one (sec, head); scatter to head layout.
    const int sec = blockIdx.x / 12;
    const int h   = blockIdx.x % 12;
    float* pn  = g_qkv + sec * TSZ;
    float* plo = g_qkv + (3 + sec) * TSZ;
    float* phi = g_qkv + (6 + sec) * TSZ;
#pragma unroll
    for (int mfi = 0; mfi < 2; mfi++) {
        const int row0 = m0 + (mw * 2 + mfi) * 16 + g;
#pragma unroll
        for (int half = 0; half < 2; half++) {
            const int mrow = row0 + half * 8;
            const int bb = mrow >> 11, tt = mrow & 2047;
            const int obase = (bb * 12 + h) * HSTRIDE + tt * 64;
#pragma unroll
            for (int nfi = 0; nfi < 4; nfi++) {
                const int d = nw * 32 + nfi * 8 + tig * 2;
                const float n0v = acc[0][mfi][nfi][half * 2], n1v = acc[0][mfi][nfi][half * 2 + 1];
                const float m0v = acc[1][mfi][nfi][half * 2], m1v = acc[1][mfi][nfi][half * 2 + 1];
                const float r0v = acc[2][mfi][nfi][half * 2], r1v = acc[2][mfi][nfi][half * 2 + 1];
                *(float2*)(pn  + obase + d) = make_float2(n0v, n1v);
                *(float2*)(plo + obase + d) = make_float2(m0v - r0v, m1v - r1v);
                *(float2*)(phi + obase + d) = make_float2(m0v + r0v, m1v + r1v);
            }
        }
    }
}

// ============================================================================
// Kernel 2: causal flash attention with TF32 mma (unchanged from R2).
// ============================================================================
__global__ void __launch_bounds__(256, 2) attn_mma() {
    __shared__ uint32_t sKf[8 * 268];
    __shared__ uint32_t sVf[32 * 64];
    __shared__ uint32_t sP[8 * 512];

    const int tid  = threadIdx.x;
    const int w    = tid >> 5;
    const int lane = tid & 31;
    const int g    = lane >> 2;
    const int tig  = lane & 3;

    const int qt = blockIdx.x;
    const int bh = blockIdx.y;
    const int z  = blockIdx.z;

    const float *Q, *K, *V;
    float* O;
    if (z == 0) {
        Q = g_qkv;  K = g_qkv + TSZ;  V = g_qkv + 2 * TSZ;  O = g_att + 8 * TSZ;
    } else {
        const int c = z - 1;
        Q = g_qkv + (3 + 3 * ((c >> 2) & 1)) * TSZ;
        K = g_qkv + (3 + 3 * ((c >> 1) & 1) + 1) * TSZ;
        V = g_qkv + (3 + 3 * (c & 1) + 2) * TSZ;
        O = g_att + c * TSZ;
    }
    const int base = bh * HSTRIDE;
    Q += base; K += base; V += base; O += base;

    const int q0   = qt * 128;
    const int q_lo = q0 + w * 16;
    const int q_hi = q_lo + 15;

    uint32_t qa[8][4];
    {
        const float* rA = Q + (q_lo + g) * 64;
        const float* rB = Q + (q_lo + g + 8) * 64;
#pragma unroll
        for (int kf = 0; kf < 8; kf++) {
            qa[kf][0] = f2tf32(rA[kf * 8 + tig] * 0.125f);
            qa[kf][1] = f2tf32(rB[kf * 8 + tig] * 0.125f);
            qa[kf][2] = f2tf32(rA[kf * 8 + tig + 4] * 0.125f);
            qa[kf][3] = f2tf32(rB[kf * 8 + tig + 4] * 0.125f);
        }
    }

    float o[8][4];
#pragma unroll
    for (int nf = 0; nf < 8; nf++)
#pragma unroll
        for (int r = 0; r < 4; r++) o[nf][r] = 0.f;
    float m0 = -1e30f, m1 = -1e30f, l0 = 0.f, l1 = 0.f;

    const int vkf = tid >> 6;
    const int vnf = (tid >> 3) & 7;
    const int vg  = tid & 7;
    const int vbase = (vkf * 8 + vnf) * 64 + vg * 8;

    const int ntiles = qt * 4 + 4;

    for (int kt = 0; kt < ntiles; kt++) {
        const int kbase = kt * 32;
        __syncthreads();
        {
            const float4* kg = (const float4*)(K + kbase * 64);
#pragma unroll
            for (int i = 0; i < 2; i++) {
                const int idx = tid + 256 * i;
                const int key = idx >> 4;
                const int d0  = (idx & 15) * 4;
                float4 v = kg[idx];
                const int kf  = d0 >> 3;
                const int rg  = (d0 >> 2) & 1;
                const int b_  = kf * 268 + (key >> 3) * 64 + (key & 7) * 8 + rg;
                sKf[b_ + 0] = f2tf32(v.x);
                sKf[b_ + 2] = f2tf32(v.y);
                sKf[b_ + 4] = f2tf32(v.z);
                sKf[b_ + 6] = f2tf32(v.w);
            }
        }
        {
            const float* vt = V + kbase * 64;
            uint32_t tmp[8];
#pragma unroll
            for (int j = 0; j < 8; j++) {
                const int key = vkf * 8 + (j & 1) * 4 + (j >> 1);
                tmp[j] = f2tf32(vt[key * 64 + vnf * 8 + vg]);
            }
            *(uint4*)&sVf[vbase]     = make_uint4(tmp[0], tmp[1], tmp[2], tmp[3]);
            *(uint4*)&sVf[vbase + 4] = make_uint4(tmp[4], tmp[5], tmp[6], tmp[7]);
        }
        __syncthreads();

        if (kbase > q_hi) continue;

        float dS[4][4];
#pragma unroll
        for (int nf = 0; nf < 4; nf++)
#pragma unroll
            for (int r = 0; r < 4; r++) dS[nf][r] = 0.f;
#pragma unroll
        for (int kf = 0; kf < 8; kf++) {
#pragma unroll
            for (int nf = 0; nf < 4; nf++) {
                uint2 kb = *(const uint2*)&sKf[kf * 268 + nf * 64 + lane * 2];
                mma_tf32(dS[nf][0], dS[nf][1], dS[nf][2], dS[nf][3],
                         qa[kf][0], qa[kf][1], qa[kf][2], qa[kf][3], kb.x, kb.y);
            }
        }

        if (kbase + 31 > q_lo) {
            const int rowA = q_lo + g, rowB = rowA + 8;
#pragma unroll
            for (int nf = 0; nf < 4; nf++) {
                const int key0 = kbase + nf * 8 + 2 * tig;
                if (key0 > rowA)     dS[nf][0] = -1e30f;
                if (key0 + 1 > rowA) dS[nf][1] = -1e30f;
                if (key0 > rowB)     dS[nf][2] = -1e30f;
                if (key0 + 1 > rowB) dS[nf][3] = -1e30f;
            }
        }

        float mt0 = -1e30f, mt1 = -1e30f;
#pragma unroll
        for (int nf = 0; nf < 4; nf++) {
            mt0 = fmaxf(mt0, fmaxf(dS[nf][0], dS[nf][1]));
            mt1 = fmaxf(mt1, fmaxf(dS[nf][2], dS[nf][3]));
        }
        mt0 = fmaxf(mt0, __shfl_xor_sync(0xffffffffu, mt0, 1));
        mt1 = fmaxf(mt1, __shfl_xor_sync(0xffffffffu, mt1, 1));
        mt0 = fmaxf(mt0, __shfl_xor_sync(0xffffffffu, mt0, 2));
        mt1 = fmaxf(mt1, __shfl_xor_sync(0xffffffffu, mt1, 2));

        const float mn0 = fmaxf(m0, mt0), mn1 = fmaxf(m1, mt1);
        const float c0 = __expf(m0 - mn0), c1 = __expf(m1 - mn1);
        m0 = mn0; m1 = mn1;
        l0 *= c0;  l1 *= c1;
#pragma unroll
        for (int nf = 0; nf < 8; nf++) {
            o[nf][0] *= c0; o[nf][1] *= c0;
            o[nf][2] *= c1; o[nf][3] *= c1;
        }

        const int pw0 = w * 512 + g * 32;
        const int rot = (g * 8);
#pragma unroll
        for (int nf = 0; nf < 4; nf++) {
            float p0 = __expf(dS[nf][0] - mn0);
            float p1 = __expf(dS[nf][1] - mn0);
            float p2 = __expf(dS[nf][2] - mn1);
            float p3 = __expf(dS[nf][3] - mn1);
            l0 += p0 + p1;
            l1 += p2 + p3;
            const int colr = (nf * 8 + tig * 2 + rot) & 31;
            *(uint2*)&sP[pw0 + colr]       = make_uint2(f2tf32(p0), f2tf32(p1));
            *(uint2*)&sP[pw0 + 256 + colr] = make_uint2(f2tf32(p2), f2tf32(p3));
        }
        __syncwarp();

        uint32_t pa[4][4];
#pragma unroll
        for (int kf = 0; kf < 4; kf++) {
            pa[kf][0] = sP[pw0 +       ((kf * 8 + tig + rot) & 31)];
            pa[kf][1] = sP[pw0 + 256 + ((kf * 8 + tig + rot) & 31)];
            pa[kf][2] = sP[pw0 +       ((kf * 8 + tig + 4 + rot) & 31)];
            pa[kf][3] = sP[pw0 + 256 + ((kf * 8 + tig + 4 + rot) & 31)];
        }

#pragma unroll
        for (int kf = 0; kf < 4; kf++) {
#pragma unroll
            for (int nf = 0; nf < 8; nf++) {
                uint2 vb = *(const uint2*)&sVf[(kf * 8 + nf) * 64 + lane * 2];
                mma_tf32(o[nf][0], o[nf][1], o[nf][2], o[nf][3],
                         pa[kf][0], pa[kf][1], pa[kf][2], pa[kf][3], vb.x, vb.y);
            }
        }
    }

    l0 += __shfl_xor_sync(0xffffffffu, l0, 1);
    l1 += __shfl_xor_sync(0xffffffffu, l1, 1);
    l0 += __shfl_xor_sync(0xffffffffu, l0, 2);
    l1 += __shfl_xor_sync(0xffffffffu, l1, 2);
    const float i0 = 1.0f / l0, i1 = 1.0f / l1;

    float* oA = O + (q_lo + g) * 64;
    float* oB = O + (q_lo + g + 8) * 64;
#pragma unroll
    for (int nf = 0; nf < 8; nf++) {
        *(float2*)&oA[nf * 8 + tig * 2] = make_float2(o[nf][0] * i0, o[nf][1] * i0);
        *(float2*)&oB[nf * 8 + tig * 2] = make_float2(o[nf][2] * i1, o[nf][3] * i1);
    }
}

// ============================================================================
// Kernel 3: elementwise min/max over the 8 interval combos (unchanged).
// ============================================================================
__global__ void __launch_bounds__(256) reduce_kernel() {
    const int i = blockIdx.x * 256 + threadIdx.x;
    float4 lo = ((const float4*)g_att)[i];
    float4 hi = lo;
#pragma unroll
    for (int c = 1; c < 8; c++) {
        float4 v = ((const float4*)(g_att + c * TSZ))[i];
        lo.x = fminf(lo.x, v.x); lo.y = fminf(lo.y, v.y);
        lo.z = fminf(lo.z, v.z); lo.w = fminf(lo.w, v.w);
        hi.x = fmaxf(hi.x, v.x); hi.y = fmaxf(hi.y, v.y);
        hi.z = fmaxf(hi.z, v.z); hi.w = fmaxf(hi.w, v.w);
    }
    ((float4*)g_red)[i] = lo;
    ((float4*)(g_red + TSZ))[i] = hi;
}

// ============================================================================
// Kernel 4: fused output projection (y, y_lo, y_hi), TF32 mma.
// M=4096 N=768 K=768; 3 A sources share one W tile. A read from head layout.
// ============================================================================
__global__ void __launch_bounds__(256, 1) proj_mma(const float* __restrict__ W,
                                                   float* __restrict__ out) {
    __shared__ uint32_t sA[3 * 2048];
    __shared__ uint32_t sB[1024];

    const int tid  = threadIdx.x;
    const int lane = tid & 31;
    const int w    = tid >> 5;
    const int g    = lane >> 2, tig = lane & 3;
    const int mw   = w >> 1, nw = w & 1;
    const int n0   = blockIdx.x * 64, m0 = blockIdx.y * 128;
    const int lrow = tid >> 2;
    const int lc   = tid & 3;

    const float* A0 = g_att + 8 * TSZ;
    const float* A1 = g_red;
    const float* A2 = g_red + TSZ;

    int rb[2];
#pragma unroll
    for (int i = 0; i < 2; i++) {
        const int m = m0 + lrow + 64 * i;
        rb[i] = (m >> 11) * (12 * HSTRIDE) + (m & 2047) * 64;
    }
    const float* pw = W + (n0 + lrow) * 768 + lc * 4;

    float acc[3][2][4][4];
#pragma unroll
    for (int t = 0; t < 3; t++)
#pragma unroll
        for (int i = 0; i < 2; i++)
#pragma unroll
            for (int j = 0; j < 4; j++)
#pragma unroll
                for (int r = 0; r < 4; r++) acc[t][i][j][r] = 0.f;

    float4 v0[2], v1[2], v2[2], vw;
    {
        const int k = lc * 4;
        const int ha = (k >> 6) * HSTRIDE + (k & 63);
        v0[0] = *(const float4*)(A0 + rb[0] + ha); v0[1] = *(const float4*)(A0 + rb[1] + ha);
        v1[0] = *(const float4*)(A1 + rb[0] + ha); v1[1] = *(const float4*)(A1 + rb[1] + ha);
        v2[0] = *(const float4*)(A2 + rb[0] + ha); v2[1] = *(const float4*)(A2 + rb[1] + ha);
        vw    = *(const float4*)pw;
    }

    for (int kt = 0; kt < 48; kt++) {
        if (kt) __syncthreads();
#pragma unroll
        for (int i = 0; i < 2; i++) {
            const int row = lrow + 64 * i;
            stA(sA,        row, lc, cvt4(v0[i]));
            stA(sA + 2048, row, lc, cvt4(v1[i]));
            stA(sA + 4096, row, lc, cvt4(v2[i]));
        }
        stB(sB, lrow, lc, cvt4(vw));
        __syncthreads();
        if (kt < 47) {
            const int k = (kt + 1) * 16 + lc * 4;
            const int ha = (k >> 6) * HSTRIDE + (k & 63);
            v0[0] = *(const float4*)(A0 + rb[0] + ha); v0[1] = *(const float4*)(A0 + rb[1] + ha);
            v1[0] = *(const float4*)(A1 + rb[0] + ha); v1[1] = *(const float4*)(A1 + rb[1] + ha);
            v2[0] = *(const float4*)(A2 + rb[0] + ha); v2[1] = *(const float4*)(A2 + rb[1] + ha);
            vw    = *(const float4*)(pw + (kt + 1) * 16);
        }
#pragma unroll
        for (int kf = 0; kf < 2; kf++) {
            uint32_t a[3][2][4];
#pragma unroll
            for (int t = 0; t < 3; t++)
#pragma unroll
                for (int mfi = 0; mfi < 2; mfi++) {
                    const int base = t * 2048 + ((mw * 2 + mfi) * 2 + kf) * 128;
#pragma unroll
                    for (int r = 0; r < 4; r++)
                        a[t][mfi][r] = sA[base + r * 32 + (lane ^ ((kf * 2 + (r >> 1)) << 3))];
                }
            uint32_t b[4][2];
#pragma unroll
            for (int nfi = 0; nfi < 4; nfi++) {
                const int base = ((nw * 4 + nfi) * 2 + kf) * 64;
#pragma unroll
                for (int r = 0; r < 2; r++)
                    b[nfi][r] = sB[base + r * 32 + (lane ^ ((kf * 2 + r) << 3))];
            }
#pragma unroll
            for (int mfi = 0; mfi < 2; mfi++)
#pragma unroll
                for (int nfi = 0; nfi < 4; nfi++) {
                    mma_tf32(acc[0][mfi][nfi][0], acc[0][mfi][nfi][1], acc[0][mfi][nfi][2], acc[0][mfi][nfi][3],
                             a[0][mfi][0], a[0][mfi][1], a[0][mfi][2], a[0][mfi][3], b[nfi][0], b[nfi][1]);
                    mma_tf32(acc[1][mfi][nfi][0], acc[1][mfi][nfi][1], acc[1][mfi][nfi][2], acc[1][mfi][nfi][3],
                             a[1][mfi][0], a[1][mfi][1], a[1][mfi][2], a[1][mfi][3], b[nfi][0], b[nfi][1]);
                    mma_tf32(acc[2][mfi][nfi][0], acc[2][mfi][nfi][1], acc[2][mfi][nfi][2], acc[2][mfi][nfi][3],
                             a[2][mfi][0], a[2][mfi][1], a[2][mfi][2], a[2][mfi][3], b[nfi][0], b[nfi][1]);
                }
        }
    }

#pragma unroll
    for (int mfi = 0; mfi < 2; mfi++) {
#pragma unroll
        for (int half = 0; half < 2; half++) {
            const int mrow = m0 + (mw * 2 + mfi) * 16 + g + half * 8;
            float* po = out + mrow * 768 + n0 + nw * 32;
#pragma unroll
            for (int nfi = 0; nfi < 4; nfi++) {
                const int d = nfi * 8 + tig * 2;
                *(float2*)(po + d)           = make_float2(acc[0][mfi][nfi][half * 2], acc[0][mfi][nfi][half * 2 + 1]);
                *(float2*)(po + TSZ + d)     = make_float2(acc[1][mfi][nfi][half * 2], acc[1][mfi][nfi][half * 2 + 1]);
                *(float2*)(po + 2 * TSZ + d) = make_float2(acc[2][mfi][nfi][half * 2], acc[2][mfi][nfi][half * 2 + 1]);
            }
        }
    }
}

extern "C" void kernel_launch(void* const* d_in, const int* in_sizes, int n_in,
                              void* d_out, int out_size) {
    const float* x  = (const float*)d_in[0];
    const float* xl = (const float*)d_in[1];
    const float* xu = (const float*)d_in[2];
    const float* Wa = (const float*)d_in[3];
    const float* Wp = (const float*)d_in[4];
    float* out = (float*)d_out;

    qkv_mma<<<dim3(36, 32), 256>>>(x, xl, xu, Wa);
    attn_mma<<<dim3(16, 24, 9), 256>>>();
    reduce_kernel<<<TSZ / 4 / 256, 256>>>();
    proj_mma<<<dim3(12, 32), 256>>>(Wp, out);
}